// round 3
// baseline (speedup 1.0000x reference)
#include <cuda_runtime.h>
#include <math.h>
#include <stdint.h>

#define B_   2
#define S_   1024
#define D_   2048
#define H_   16
#define KV_  4
#define HD_  128
#define MTOK 2048      // B*S tokens
#define NQ   2048      // H*HD
#define NKV  512       // KV*HD
#define KDIM 2048

// ---------------- scratch (static __device__, no allocs) ----------------
__device__ int8_t g_x8r[MTOK*D_], g_x8i[MTOK*D_];
__device__ float  g_xscale[MTOK];

__device__ int8_t g_wq_r[NQ*D_],  g_wq_i[NQ*D_];
__device__ int8_t g_wk_r[NKV*D_], g_wk_i[NKV*D_];
__device__ int8_t g_wv_r[NKV*D_], g_wv_i[NKV*D_];
__device__ int8_t g_wo_r[D_*NQ],  g_wo_i[D_*NQ];

__device__ float g_mag[4];
__device__ float g_part[4][256];

__device__ float g_q_re[MTOK*NQ],  g_q_im[MTOK*NQ];
__device__ float g_k_re[MTOK*NKV], g_k_im[MTOK*NKV];
__device__ float g_v_re[MTOK*NKV], g_v_im[MTOK*NKV];
__device__ float g_o_re[MTOK*NQ],  g_o_im[MTOK*NQ];
__device__ int8_t g_o8r[MTOK*NQ],  g_o8i[MTOK*NQ];
__device__ float g_oscale[MTOK];

// ---------------- weight magnitude (deterministic 2-stage) ----------------
__global__ void mag_partial(const float* __restrict__ a, const float* __restrict__ b,
                            int n, int slot) {
    __shared__ float red[256];
    float s = 0.f;
    for (int i = blockIdx.x * blockDim.x + threadIdx.x; i < n;
         i += gridDim.x * blockDim.x) {
        float ar = a[i], br = b[i];
        s += sqrtf(ar * ar + br * br);
    }
    red[threadIdx.x] = s;
    __syncthreads();
    for (int st = 128; st > 0; st >>= 1) {
        if (threadIdx.x < st) red[threadIdx.x] += red[threadIdx.x + st];
        __syncthreads();
    }
    if (threadIdx.x == 0) g_part[slot][blockIdx.x] = red[0];
}

__global__ void mag_final() {
    int t = threadIdx.x;
    if (t < 4) {
        float s = 0.f;
        for (int i = 0; i < 256; i++) s += g_part[t][i];
        const float cnt[4] = {4194304.f, 1048576.f, 1048576.f, 4194304.f};
        g_mag[t] = s / cnt[t];
    }
}

// ---------------- ternarize + transpose weights: [K,N] fp32 -> [N,K] int8 ----------------
__global__ void tern_T(const float* __restrict__ wr, const float* __restrict__ wi,
                       int sel, int K, int N) {
    int8_t *dr, *di;
    if (sel == 0)      { dr = g_wq_r; di = g_wq_i; }
    else if (sel == 1) { dr = g_wk_r; di = g_wk_i; }
    else if (sel == 2) { dr = g_wv_r; di = g_wv_i; }
    else               { dr = g_wo_r; di = g_wo_i; }
    __shared__ float tr[32][33], ti[32][33];
    int n0 = blockIdx.x * 32, k0 = blockIdx.y * 32;
#pragma unroll
    for (int j = 0; j < 4; j++) {
        int k = k0 + threadIdx.y + 8 * j;
        tr[threadIdx.y + 8 * j][threadIdx.x] = wr[(size_t)k * N + n0 + threadIdx.x];
        ti[threadIdx.y + 8 * j][threadIdx.x] = wi[(size_t)k * N + n0 + threadIdx.x];
    }
    __syncthreads();
#pragma unroll
    for (int j = 0; j < 4; j++) {
        int n = n0 + threadIdx.y + 8 * j;
        int k = k0 + threadIdx.x;
        float a = tr[threadIdx.x][threadIdx.y + 8 * j];
        float b = ti[threadIdx.x][threadIdx.y + 8 * j];
        int8_t r = 0, m = 0;
        if (fabsf(a) >= fabsf(b)) r = (a > 0.f) ? 1 : ((a < 0.f) ? -1 : 0);
        else                      m = (b > 0.f) ? 1 : ((b < 0.f) ? -1 : 0);
        dr[(size_t)n * K + k] = r;
        di[(size_t)n * K + k] = m;
    }
}

// ---------------- per-token activation quantization ----------------
__global__ void act_quant_k(const float* __restrict__ xr_in,
                            const float* __restrict__ xi_in, int sel) {
    const float *xr, *xi; int8_t *qr, *qi; float* sc;
    if (sel == 0) { xr = xr_in;  xi = xi_in;  qr = g_x8r; qi = g_x8i; sc = g_xscale; }
    else          { xr = g_o_re; xi = g_o_im; qr = g_o8r; qi = g_o8i; sc = g_oscale; }
    const int K = 2048;
    int t = blockIdx.x;
    size_t base = (size_t)t * K;
    __shared__ float red[256];
    __shared__ float s_sh;
    float mx = 0.f;
    for (int i = threadIdx.x; i < K; i += 256)
        mx = fmaxf(mx, fmaxf(fabsf(xr[base + i]), fabsf(xi[base + i])));
    red[threadIdx.x] = mx;
    __syncthreads();
    for (int st = 128; st > 0; st >>= 1) {
        if (threadIdx.x < st) red[threadIdx.x] = fmaxf(red[threadIdx.x], red[threadIdx.x + st]);
        __syncthreads();
    }
    if (threadIdx.x == 0) {
        float s = 127.f / fmaxf(red[0], 1e-5f);
        s_sh = s;
        sc[t] = 1.f / s;
    }
    __syncthreads();
    float s = s_sh;
    for (int i = threadIdx.x; i < K; i += 256) {
        float vr = rintf(xr[base + i] * s); vr = fminf(fmaxf(vr, -128.f), 127.f);
        float vi = rintf(xi[base + i] * s); vi = fminf(fmaxf(vi, -128.f), 127.f);
        qr[base + i] = (int8_t)(int)vr;
        qi[base + i] = (int8_t)(int)vi;
    }
}

// ---------------- complex int8 GEMM (dp4a), exact integer core ----------------
// A: [M,K] int8 (re,im), B: [N,K] int8 ternary (re,im)
// out_re = (rr - ii) * mag/s_tok ; out_im = (ri + ir) * mag/s_tok
__global__ void __launch_bounds__(256) gemm_i8_cplx(int sel,
                                                    float* __restrict__ outr_p,
                                                    float* __restrict__ outi_p) {
    const int8_t *Ar, *Ai, *Br, *Bi; const float* ts; float *Or, *Oi; int N;
    if (sel == 0)      { Ar=g_x8r; Ai=g_x8i; Br=g_wq_r; Bi=g_wq_i; ts=g_xscale; Or=g_q_re; Oi=g_q_im; N=NQ;  }
    else if (sel == 1) { Ar=g_x8r; Ai=g_x8i; Br=g_wk_r; Bi=g_wk_i; ts=g_xscale; Or=g_k_re; Oi=g_k_im; N=NKV; }
    else if (sel == 2) { Ar=g_x8r; Ai=g_x8i; Br=g_wv_r; Bi=g_wv_i; ts=g_xscale; Or=g_v_re; Oi=g_v_im; N=NKV; }
    else               { Ar=g_o8r; Ai=g_o8i; Br=g_wo_r; Bi=g_wo_i; ts=g_oscale; Or=outr_p; Oi=outi_p; N=NQ;  }
    const int K = KDIM;
    __shared__ int sar[16][64], sai[16][64], sbr[16][64], sbi[16][64]; // char4-as-int, k-group-major
    int tid = threadIdx.x;
    int tx = tid & 15, ty = tid >> 4;
    int m0 = blockIdx.y << 6, n0 = blockIdx.x << 6;
    int accrr[4][4], accii[4][4], accri[4][4], accir[4][4];
#pragma unroll
    for (int a = 0; a < 4; a++)
#pragma unroll
        for (int b2 = 0; b2 < 4; b2++) { accrr[a][b2]=0; accii[a][b2]=0; accri[a][b2]=0; accir[a][b2]=0; }
    int lrow = tid >> 2;
    int kb = (tid & 3) << 4;      // byte offset in 64-byte chunk
    int kg = kb >> 2;             // char4-group index
    for (int kc = 0; kc < K; kc += 64) {
        int4 v;
        v = *(const int4*)(Ar + (size_t)(m0 + lrow) * K + kc + kb);
        sar[kg+0][lrow]=v.x; sar[kg+1][lrow]=v.y; sar[kg+2][lrow]=v.z; sar[kg+3][lrow]=v.w;
        v = *(const int4*)(Ai + (size_t)(m0 + lrow) * K + kc + kb);
        sai[kg+0][lrow]=v.x; sai[kg+1][lrow]=v.y; sai[kg+2][lrow]=v.z; sai[kg+3][lrow]=v.w;
        v = *(const int4*)(Br + (size_t)(n0 + lrow) * K + kc + kb);
        sbr[kg+0][lrow]=v.x; sbr[kg+1][lrow]=v.y; sbr[kg+2][lrow]=v.z; sbr[kg+3][lrow]=v.w;
        v = *(const int4*)(Bi + (size_t)(n0 + lrow) * K + kc + kb);
        sbi[kg+0][lrow]=v.x; sbi[kg+1][lrow]=v.y; sbi[kg+2][lrow]=v.z; sbi[kg+3][lrow]=v.w;
        __syncthreads();
#pragma unroll 4
        for (int kk = 0; kk < 16; kk++) {
            int4 AR = *(const int4*)&sar[kk][ty << 2];
            int4 AI = *(const int4*)&sai[kk][ty << 2];
            int4 BR = *(const int4*)&sbr[kk][tx << 2];
            int4 BI = *(const int4*)&sbi[kk][tx << 2];
            int arv[4] = {AR.x, AR.y, AR.z, AR.w};
            int aiv[4] = {AI.x, AI.y, AI.z, AI.w};
            int brv[4] = {BR.x, BR.y, BR.z, BR.w};
            int biv[4] = {BI.x, BI.y, BI.z, BI.w};
#pragma unroll
            for (int a = 0; a < 4; a++)
#pragma unroll
                for (int b2 = 0; b2 < 4; b2++) {
                    accrr[a][b2] = __dp4a(arv[a], brv[b2], accrr[a][b2]);
                    accii[a][b2] = __dp4a(aiv[a], biv[b2], accii[a][b2]);
                    accri[a][b2] = __dp4a(arv[a], biv[b2], accri[a][b2]);
                    accir[a][b2] = __dp4a(aiv[a], brv[b2], accir[a][b2]);
                }
        }
        __syncthreads();
    }
    float mg = g_mag[sel];
#pragma unroll
    for (int a = 0; a < 4; a++) {
        int mrow = m0 + (ty << 2) + a;
        float sc = mg * ts[mrow];
#pragma unroll
        for (int b2 = 0; b2 < 4; b2++) {
            int nn = n0 + (tx << 2) + b2;
            Or[(size_t)mrow * N + nn] = (float)(accrr[a][b2] - accii[a][b2]) * sc;
            Oi[(size_t)mrow * N + nn] = (float)(accri[a][b2] + accir[a][b2]) * sc;
        }
    }
}

// ---------------- RoPE (in-place, real component only) ----------------
__global__ void rope_k(int sel) {
    float* x; int nh;
    if (sel == 0) { x = g_q_re; nh = H_; } else { x = g_k_re; nh = KV_; }
    int total = MTOK * nh * 64;
    int idx = blockIdx.x * blockDim.x + threadIdx.x;
    if (idx >= total) return;
    int d = idx & 63;
    int th = idx >> 6;
    int head = th % nh;
    int tok = th / nh;
    int pos = tok & (S_ - 1);
    float inv = (float)exp(-log(10000.0) * (double)d / 64.0);
    float ang = (float)pos * inv;
    float c = cosf(ang), sn = sinf(ang);
    size_t off = (size_t)tok * (nh * HD_) + head * HD_;
    float x0 = x[off + d], x1 = x[off + d + 64];
    x[off + d]      = x0 * c - x1 * sn;
    x[off + d + 64] = x1 * c + x0 * sn;
}

// ---------------- causal attention (fp32, online softmax) ----------------
// grid: (S/8, B*H), block 256 (8 warps, 1 q-row per warp)
__global__ void __launch_bounds__(256) attn_k() {
    __shared__ float sq_r[8][HD_], sq_i[8][HD_];
    __shared__ float sT_r[HD_][33], sT_i[HD_][33];   // K tile then V tile, transposed
    int tid = threadIdx.x;
    int lane = tid & 31, w = tid >> 5;
    int b = blockIdx.y >> 4, h = blockIdx.y & 15;
    int kvh = h >> 2;  // GROUPS = 4
    int row = (blockIdx.x << 3) + w;
    int rowmax = (blockIdx.x << 3) + 7;
    size_t qoff = ((size_t)(b * S_ + row)) * NQ + h * HD_;
    for (int i = lane; i < HD_; i += 32) {
        sq_r[w][i] = g_q_re[qoff + i];
        sq_i[w][i] = g_q_im[qoff + i];
    }
    float m = -INFINITY, l = 0.f;
    float o_r[4] = {0.f, 0.f, 0.f, 0.f}, o_i[4] = {0.f, 0.f, 0.f, 0.f};
    const float scale = 1.0f / sqrtf((float)HD_);
    int nch = (rowmax >> 5) + 1;
    size_t kvbase = (size_t)(b * S_) * NKV + kvh * HD_;
    for (int c = 0; c < nch; c++) {
        int k0 = c << 5;
        __syncthreads();  // prior PV reads done (and sq visible on first iter)
#pragma unroll
        for (int i = 0; i < 16; i++) {          // load K tile transposed
            int e = tid + (i << 8);
            int key = e >> 7, d = e & 127;
            size_t g = kvbase + (size_t)(k0 + key) * NKV + d;
            sT_r[d][key] = g_k_re[g];
            sT_i[d][key] = g_k_im[g];
        }
        __syncthreads();
        float p = 0.f;
        if (k0 <= row) {
            float s = 0.f;
            const float4* q4r = (const float4*)sq_r[w];
            const float4* q4i = (const float4*)sq_i[w];
#pragma unroll 8
            for (int i4 = 0; i4 < 32; i4++) {
                float4 a = q4r[i4], bb = q4i[i4];
                int i = i4 << 2;
                s += a.x * sT_r[i][lane]   + a.y * sT_r[i+1][lane]
                   + a.z * sT_r[i+2][lane] + a.w * sT_r[i+3][lane];
                s += bb.x * sT_i[i][lane]   + bb.y * sT_i[i+1][lane]
                   + bb.z * sT_i[i+2][lane] + bb.w * sT_i[i+3][lane];
            }
            s *= scale;
            if (k0 + lane > row) s = -INFINITY;
            float cm = s;
#pragma unroll
            for (int off = 16; off; off >>= 1)
                cm = fmaxf(cm, __shfl_xor_sync(0xffffffffu, cm, off));
            float mnew = fmaxf(m, cm);
            p = expf(s - mnew);
            float corr = expf(m - mnew);
            float ps = p;
#pragma unroll
            for (int off = 16; off; off >>= 1)
                ps += __shfl_xor_sync(0xffffffffu, ps, off);
            l = l * corr + ps;
#pragma unroll
            for (int i = 0; i < 4; i++) { o_r[i] *= corr; o_i[i] *= corr; }
            m = mnew;
        }
        __syncthreads();  // scores done reading K tile
#pragma unroll
        for (int i = 0; i < 16; i++) {          // load V tile transposed (reuse buffer)
            int e = tid + (i << 8);
            int key = e >> 7, d = e & 127;
            size_t g = kvbase + (size_t)(k0 + key) * NKV + d;
            sT_r[d][key] = g_v_re[g];
            sT_i[d][key] = g_v_im[g];
        }
        __syncthreads();
        if (k0 <= row) {
#pragma unroll 8
            for (int j = 0; j < 32; j++) {
                float pj = __shfl_sync(0xffffffffu, p, j);
#pragma unroll
                for (int i = 0; i < 4; i++) {
                    o_r[i] += pj * sT_r[lane + (i << 5)][j];
                    o_i[i] += pj * sT_i[lane + (i << 5)][j];
                }
            }
        }
    }
    float invl = 1.f / l;
#pragma unroll
    for (int i = 0; i < 4; i++) {
        g_o_re[qoff + lane + (i << 5)] = o_r[i] * invl;
        g_o_im[qoff + lane + (i << 5)] = o_i[i] * invl;
    }
}

// ---------------- launch ----------------
extern "C" void kernel_launch(void* const* d_in, const int* in_sizes, int n_in,
                              void* d_out, int out_size) {
    const float* hr  = (const float*)d_in[0];
    const float* hi  = (const float*)d_in[1];
    const float* wqr = (const float*)d_in[2];
    const float* wqi = (const float*)d_in[3];
    const float* wkr = (const float*)d_in[4];
    const float* wki = (const float*)d_in[5];
    const float* wvr = (const float*)d_in[6];
    const float* wvi = (const float*)d_in[7];
    const float* wor = (const float*)d_in[8];
    const float* woi = (const float*)d_in[9];
    float* out = (float*)d_out;

    mag_partial<<<256, 256>>>(wqr, wqi, D_ * NQ, 0);
    mag_partial<<<256, 256>>>(wkr, wki, D_ * NKV, 1);
    mag_partial<<<256, 256>>>(wvr, wvi, D_ * NKV, 2);
    mag_partial<<<256, 256>>>(wor, woi, NQ * D_, 3);
    mag_final<<<1, 32>>>();

    dim3 tb(32, 8);
    tern_T<<<dim3(NQ / 32, D_ / 32), tb>>>(wqr, wqi, 0, D_, NQ);
    tern_T<<<dim3(NKV / 32, D_ / 32), tb>>>(wkr, wki, 1, D_, NKV);
    tern_T<<<dim3(NKV / 32, D_ / 32), tb>>>(wvr, wvi, 2, D_, NKV);
    tern_T<<<dim3(D_ / 32, NQ / 32), tb>>>(wor, woi, 3, NQ, D_);

    act_quant_k<<<MTOK, 256>>>(hr, hi, 0);

    gemm_i8_cplx<<<dim3(NQ / 64, MTOK / 64), 256>>>(0, nullptr, nullptr);
    gemm_i8_cplx<<<dim3(NKV / 64, MTOK / 64), 256>>>(1, nullptr, nullptr);
    gemm_i8_cplx<<<dim3(NKV / 64, MTOK / 64), 256>>>(2, nullptr, nullptr);

    rope_k<<<(MTOK * H_ * 64) / 256, 256>>>(0);
    rope_k<<<(MTOK * KV_ * 64) / 256, 256>>>(1);

    attn_k<<<dim3(S_ / 8, B_ * H_), 256>>>();

    act_quant_k<<<MTOK, 256>>>(nullptr, nullptr, 1);

    gemm_i8_cplx<<<dim3(NQ / 64, MTOK / 64), 256>>>(3, out, out + (size_t)B_ * S_ * D_);
}

// round 10
// speedup vs baseline: 1.1746x; 1.1746x over previous
#include <cuda_runtime.h>
#include <cuda_fp16.h>
#include <mma.h>
#include <math.h>
#include <stdint.h>

using namespace nvcuda;

#define B_   2
#define S_   1024
#define D_   2048
#define H_   16
#define KV_  4
#define HD_  128
#define MTOK 2048      // B*S tokens
#define NQ   2048      // H*HD
#define NKV  512       // KV*HD
#define KDIM 2048

// ---------------- scratch (static __device__, no allocs) ----------------
// activations: separate re/im planes, f16 ints (R3 layout, f16 type)
__device__ __align__(16) __half g_xhr[MTOK*D_], g_xhi[MTOK*D_];
__device__ float  g_xscale[MTOK];
__device__ __align__(16) __half g_ohr[MTOK*NQ], g_ohi[MTOK*NQ];
__device__ float  g_oscale[MTOK];

// ternary f16 weights, [N][K] K-contiguous, separate planes (R3 layout, f16 type)
__device__ __align__(16) __half g_wq_r[NQ*D_],  g_wq_i[NQ*D_];
__device__ __align__(16) __half g_wk_r[NKV*D_], g_wk_i[NKV*D_];
__device__ __align__(16) __half g_wv_r[NKV*D_], g_wv_i[NKV*D_];
__device__ __align__(16) __half g_wo_r[D_*NQ],  g_wo_i[D_*NQ];

__device__ float g_mag[4];
__device__ float g_part[4][256];

__device__ float g_q_re[MTOK*NQ],  g_q_im[MTOK*NQ];
__device__ float g_k_re[MTOK*NKV], g_k_im[MTOK*NKV];
__device__ float g_v_re[MTOK*NKV], g_v_im[MTOK*NKV];
__device__ float g_o_re[MTOK*NQ],  g_o_im[MTOK*NQ];

// ---------------- weight magnitude (deterministic 2-stage, R3 verbatim) ----------------
__global__ void mag_partial(const float* __restrict__ a, const float* __restrict__ b,
                            int n, int slot) {
    __shared__ float red[256];
    float s = 0.f;
    for (int i = blockIdx.x * blockDim.x + threadIdx.x; i < n;
         i += gridDim.x * blockDim.x) {
        float ar = a[i], br = b[i];
        s += sqrtf(ar * ar + br * br);
    }
    red[threadIdx.x] = s;
    __syncthreads();
    for (int st = 128; st > 0; st >>= 1) {
        if (threadIdx.x < st) red[threadIdx.x] += red[threadIdx.x + st];
        __syncthreads();
    }
    if (threadIdx.x == 0) g_part[slot][blockIdx.x] = red[0];
}

__global__ void mag_final() {
    int t = threadIdx.x;
    if (t < 4) {
        float s = 0.f;
        for (int i = 0; i < 256; i++) s += g_part[t][i];
        const float cnt[4] = {4194304.f, 1048576.f, 1048576.f, 4194304.f};
        g_mag[t] = s / cnt[t];
    }
}

// ---------------- ternarize + transpose weights: [K,N] fp32 -> [N,K] f16 (R3 structure) ----------------
__global__ void tern_T(const float* __restrict__ wr, const float* __restrict__ wi,
                       int sel, int K, int N) {
    __half *dr, *di;
    if (sel == 0)      { dr = g_wq_r; di = g_wq_i; }
    else if (sel == 1) { dr = g_wk_r; di = g_wk_i; }
    else if (sel == 2) { dr = g_wv_r; di = g_wv_i; }
    else               { dr = g_wo_r; di = g_wo_i; }
    __shared__ float tr[32][33], ti[32][33];
    int n0 = blockIdx.x * 32, k0 = blockIdx.y * 32;
#pragma unroll
    for (int j = 0; j < 4; j++) {
        int k = k0 + threadIdx.y + 8 * j;
        tr[threadIdx.y + 8 * j][threadIdx.x] = wr[(size_t)k * N + n0 + threadIdx.x];
        ti[threadIdx.y + 8 * j][threadIdx.x] = wi[(size_t)k * N + n0 + threadIdx.x];
    }
    __syncthreads();
#pragma unroll
    for (int j = 0; j < 4; j++) {
        int n = n0 + threadIdx.y + 8 * j;
        int k = k0 + threadIdx.x;
        float a = tr[threadIdx.x][threadIdx.y + 8 * j];
        float b = ti[threadIdx.x][threadIdx.y + 8 * j];
        float r = 0.f, m = 0.f;
        if (fabsf(a) >= fabsf(b)) r = (a > 0.f) ? 1.f : ((a < 0.f) ? -1.f : 0.f);
        else                      m = (b > 0.f) ? 1.f : ((b < 0.f) ? -1.f : 0.f);
        dr[(size_t)n * K + k] = __float2half_rn(r);
        di[(size_t)n * K + k] = __float2half_rn(m);
    }
}

// ---------------- per-token activation quantization (R3 structure, f16 output) ----------------
__global__ void act_quant_k(const float* __restrict__ xr_in,
                            const float* __restrict__ xi_in, int sel) {
    const float *xr, *xi; __half *qr, *qi; float* sc;
    if (sel == 0) { xr = xr_in;  xi = xi_in;  qr = g_xhr; qi = g_xhi; sc = g_xscale; }
    else          { xr = g_o_re; xi = g_o_im; qr = g_ohr; qi = g_ohi; sc = g_oscale; }
    const int K = 2048;
    int t = blockIdx.x;
    size_t base = (size_t)t * K;
    __shared__ float red[256];
    __shared__ float s_sh;
    float mx = 0.f;
    for (int i = threadIdx.x; i < K; i += 256)
        mx = fmaxf(mx, fmaxf(fabsf(xr[base + i]), fabsf(xi[base + i])));
    red[threadIdx.x] = mx;
    __syncthreads();
    for (int st = 128; st > 0; st >>= 1) {
        if (threadIdx.x < st) red[threadIdx.x] = fmaxf(red[threadIdx.x], red[threadIdx.x + st]);
        __syncthreads();
    }
    if (threadIdx.x == 0) {
        float s = 127.f / fmaxf(red[0], 1e-5f);
        s_sh = s;
        sc[t] = 1.f / s;
    }
    __syncthreads();
    float s = s_sh;
    for (int i = threadIdx.x; i < K; i += 256) {
        float vr = rintf(xr[base + i] * s); vr = fminf(fmaxf(vr, -128.f), 127.f);
        float vi = rintf(xi[base + i] * s); vi = fminf(fmaxf(vi, -128.f), 127.f);
        qr[base + i] = __float2half_rn(vr);   // exact: integer in [-128,127]
        qi[base + i] = __float2half_rn(vi);
    }
}

// ---------------- complex WMMA GEMM (R3 wiring, tensor-core engine) ----------------
// A: [M,K] f16-int (re,im), B: [N,K] f16 ternary (re,im)
// out_re = (A_r.B_r - A_i.B_i) * mag/s_tok ; out_im = (A_r.B_i + A_i.B_r) * mag/s_tok
// block: 128 thr = 4 warps (2x2), block tile 64x64, warp tile 32x32, BK=32.
#define SW 80   // smem row stride in halfs (160B: 32B-aligned rows)
__global__ void __launch_bounds__(128) gemm_cplx_wmma(int sel,
                                                      float* __restrict__ outr_p,
                                                      float* __restrict__ outi_p) {
    const __half *Ar, *Ai, *Br, *Bi; const float* ts; float *Or, *Oi; int N;
    if (sel == 0)      { Ar=g_xhr; Ai=g_xhi; Br=g_wq_r; Bi=g_wq_i; ts=g_xscale; Or=g_q_re; Oi=g_q_im; N=NQ;  }
    else if (sel == 1) { Ar=g_xhr; Ai=g_xhi; Br=g_wk_r; Bi=g_wk_i; ts=g_xscale; Or=g_k_re; Oi=g_k_im; N=NKV; }
    else if (sel == 2) { Ar=g_xhr; Ai=g_xhi; Br=g_wv_r; Bi=g_wv_i; ts=g_xscale; Or=g_v_re; Oi=g_v_im; N=NKV; }
    else               { Ar=g_ohr; Ai=g_ohi; Br=g_wo_r; Bi=g_wo_i; ts=g_oscale; Or=outr_p; Oi=outi_p; N=NQ;  }
    __shared__ __align__(16) __half pool[4][64][SW];   // Ar, Ai, Br, Bi tiles
    int tid = threadIdx.x, lane = tid & 31, wid = tid >> 5;
    int wm = wid >> 1, wn = wid & 1;
    int m0 = blockIdx.y << 6, n0 = blockIdx.x << 6;

    wmma::fragment<wmma::matrix_a, 16, 16, 16, __half, wmma::row_major> fa_r[2], fa_i[2];
    wmma::fragment<wmma::matrix_b, 16, 16, 16, __half, wmma::col_major> fb_r[2], fb_i[2], nfb;
    wmma::fragment<wmma::accumulator, 16, 16, 16, float> fcre[2][2], fcim[2][2];
#pragma unroll
    for (int a = 0; a < 2; a++)
#pragma unroll
        for (int b = 0; b < 2; b++) {
            wmma::fill_fragment(fcre[a][b], 0.0f);
            wmma::fill_fragment(fcim[a][b], 0.0f);
        }

    // loader: thread covers row r_ld (0..63), 16-half chunk hh (0/1) in each plane
    int r_ld = tid >> 1;
    int hh = (tid & 1) << 4;                   // half offset 0 or 16
    int4 ra_r[2], ra_i[2], rb_r[2], rb_i[2];
    {
        const int4* par = (const int4*)(Ar + (size_t)(m0 + r_ld) * KDIM + hh);
        const int4* pai = (const int4*)(Ai + (size_t)(m0 + r_ld) * KDIM + hh);
        const int4* pbr = (const int4*)(Br + (size_t)(n0 + r_ld) * KDIM + hh);
        const int4* pbi = (const int4*)(Bi + (size_t)(n0 + r_ld) * KDIM + hh);
        ra_r[0]=par[0]; ra_r[1]=par[1];  ra_i[0]=pai[0]; ra_i[1]=pai[1];
        rb_r[0]=pbr[0]; rb_r[1]=pbr[1];  rb_i[0]=pbi[0]; rb_i[1]=pbi[1];
    }

    const int NS = KDIM / 32;                  // 64 stages
    for (int s = 0; s < NS; s++) {
        __syncthreads();                       // previous compute done (WAR)
        *(int4*)&pool[0][r_ld][hh]     = ra_r[0];
        *(int4*)&pool[0][r_ld][hh + 8] = ra_r[1];
        *(int4*)&pool[1][r_ld][hh]     = ra_i[0];
        *(int4*)&pool[1][r_ld][hh + 8] = ra_i[1];
        *(int4*)&pool[2][r_ld][hh]     = rb_r[0];
        *(int4*)&pool[2][r_ld][hh + 8] = rb_r[1];
        *(int4*)&pool[3][r_ld][hh]     = rb_i[0];
        *(int4*)&pool[3][r_ld][hh + 8] = rb_i[1];
        __syncthreads();                       // tiles visible (RAW)
        if (s + 1 < NS) {
            size_t kc = (size_t)(s + 1) << 5;
            const int4* par = (const int4*)(Ar + (size_t)(m0 + r_ld) * KDIM + kc + hh);
            const int4* pai = (const int4*)(Ai + (size_t)(m0 + r_ld) * KDIM + kc + hh);
            const int4* pbr = (const int4*)(Br + (size_t)(n0 + r_ld) * KDIM + kc + hh);
            const int4* pbi = (const int4*)(Bi + (size_t)(n0 + r_ld) * KDIM + kc + hh);
            ra_r[0]=par[0]; ra_r[1]=par[1];  ra_i[0]=pai[0]; ra_i[1]=pai[1];
            rb_r[0]=pbr[0]; rb_r[1]=pbr[1];  rb_i[0]=pbi[0]; rb_i[1]=pbi[1];
        }
#pragma unroll
        for (int k = 0; k < 2; k++) {
            int kh = k << 4;
#pragma unroll
            for (int mi = 0; mi < 2; mi++) {
                wmma::load_matrix_sync(fa_r[mi], &pool[0][(wm << 5) + (mi << 4)][kh], SW);
                wmma::load_matrix_sync(fa_i[mi], &pool[1][(wm << 5) + (mi << 4)][kh], SW);
            }
#pragma unroll
            for (int ni = 0; ni < 2; ni++) {
                wmma::load_matrix_sync(fb_r[ni], &pool[2][(wn << 5) + (ni << 4)][kh], SW);
                wmma::load_matrix_sync(fb_i[ni], &pool[3][(wn << 5) + (ni << 4)][kh], SW);
            }
#pragma unroll
            for (int ni = 0; ni < 2; ni++) {
                nfb = fb_i[ni];
#pragma unroll
                for (int e = 0; e < nfb.num_elements; e++) nfb.x[e] = __hneg(nfb.x[e]);
#pragma unroll
                for (int mi = 0; mi < 2; mi++) {
                    wmma::mma_sync(fcre[mi][ni], fa_r[mi], fb_r[ni], fcre[mi][ni]);
                    wmma::mma_sync(fcre[mi][ni], fa_i[mi], nfb,     fcre[mi][ni]);
                    wmma::mma_sync(fcim[mi][ni], fa_r[mi], fb_i[ni], fcim[mi][ni]);
                    wmma::mma_sync(fcim[mi][ni], fa_i[mi], fb_r[ni], fcim[mi][ni]);
                }
            }
        }
    }

    // ---------------- epilogue: per-warp smem patch, scaled float4 stores ----------------
    __syncthreads();
    float* sC = (float*)&pool[0][0][0] + wid * 256;   // 256 floats per warp (1KB)
    float mg = g_mag[sel];
    int r = lane >> 1, c0 = (lane & 1) << 3;
#pragma unroll
    for (int mi = 0; mi < 2; mi++) {
#pragma unroll
        for (int ni = 0; ni < 2; ni++) {
            int grow = m0 + (wm << 5) + (mi << 4) + r;
            int gcol = n0 + (wn << 5) + (ni << 4) + c0;
            float sc = mg * ts[grow];
            size_t gb = (size_t)grow * N + gcol;

            wmma::store_matrix_sync(sC, fcre[mi][ni], 16, wmma::mem_row_major);
            __syncwarp();
            {
                const float* src = sC + r * 16 + c0;
                float4 o1, o2;
                o1.x = src[0]*sc; o1.y = src[1]*sc; o1.z = src[2]*sc; o1.w = src[3]*sc;
                o2.x = src[4]*sc; o2.y = src[5]*sc; o2.z = src[6]*sc; o2.w = src[7]*sc;
                *(float4*)(Or + gb)     = o1;
                *(float4*)(Or + gb + 4) = o2;
            }
            __syncwarp();
            wmma::store_matrix_sync(sC, fcim[mi][ni], 16, wmma::mem_row_major);
            __syncwarp();
            {
                const float* src = sC + r * 16 + c0;
                float4 o1, o2;
                o1.x = src[0]*sc; o1.y = src[1]*sc; o1.z = src[2]*sc; o1.w = src[3]*sc;
                o2.x = src[4]*sc; o2.y = src[5]*sc; o2.z = src[6]*sc; o2.w = src[7]*sc;
                *(float4*)(Oi + gb)     = o1;
                *(float4*)(Oi + gb + 4) = o2;
            }
            __syncwarp();
        }
    }
}

// ---------------- RoPE (R3 verbatim) ----------------
__global__ void rope_k(int sel) {
    float* x; int nh;
    if (sel == 0) { x = g_q_re; nh = H_; } else { x = g_k_re; nh = KV_; }
    int total = MTOK * nh * 64;
    int idx = blockIdx.x * blockDim.x + threadIdx.x;
    if (idx >= total) return;
    int d = idx & 63;
    int th = idx >> 6;
    int head = th % nh;
    int tok = th / nh;
    int pos = tok & (S_ - 1);
    float inv = (float)exp(-log(10000.0) * (double)d / 64.0);
    float ang = (float)pos * inv;
    float c = cosf(ang), sn = sinf(ang);
    size_t off = (size_t)tok * (nh * HD_) + head * HD_;
    float x0 = x[off + d], x1 = x[off + d + 64];
    x[off + d]      = x0 * c - x1 * sn;
    x[off + d + 64] = x1 * c + x0 * sn;
}

// ---------------- causal attention (R3 verbatim) ----------------
__global__ void __launch_bounds__(256) attn_k() {
    __shared__ float sq_r[8][HD_], sq_i[8][HD_];
    __shared__ float sT_r[HD_][33], sT_i[HD_][33];
    int tid = threadIdx.x;
    int lane = tid & 31, w = tid >> 5;
    int b = blockIdx.y >> 4, h = blockIdx.y & 15;
    int kvh = h >> 2;
    int row = (blockIdx.x << 3) + w;
    int rowmax = (blockIdx.x << 3) + 7;
    size_t qoff = ((size_t)(b * S_ + row)) * NQ + h * HD_;
    for (int i = lane; i < HD_; i += 32) {
        sq_r[w][i] = g_q_re[qoff + i];
        sq_i[w][i] = g_q_im[qoff + i];
    }
    float m = -INFINITY, l = 0.f;
    float o_r[4] = {0.f, 0.f, 0.f, 0.f}, o_i[4] = {0.f, 0.f, 0.f, 0.f};
    const float scale = 1.0f / sqrtf((float)HD_);
    int nch = (rowmax >> 5) + 1;
    size_t kvbase = (size_t)(b * S_) * NKV + kvh * HD_;
    for (int c = 0; c < nch; c++) {
        int k0 = c << 5;
        __syncthreads();
#pragma unroll
        for (int i = 0; i < 16; i++) {
            int e = tid + (i << 8);
            int key = e >> 7, d = e & 127;
            size_t g = kvbase + (size_t)(k0 + key) * NKV + d;
            sT_r[d][key] = g_k_re[g];
            sT_i[d][key] = g_k_im[g];
        }
        __syncthreads();
        float p = 0.f;
        if (k0 <= row) {
            float s = 0.f;
            const float4* q4r = (const float4*)sq_r[w];
            const float4* q4i = (const float4*)sq_i[w];
#pragma unroll 8
            for (int i4 = 0; i4 < 32; i4++) {
                float4 a = q4r[i4], bb = q4i[i4];
                int i = i4 << 2;
                s += a.x * sT_r[i][lane]   + a.y * sT_r[i+1][lane]
                   + a.z * sT_r[i+2][lane] + a.w * sT_r[i+3][lane];
                s += bb.x * sT_i[i][lane]   + bb.y * sT_i[i+1][lane]
                   + bb.z * sT_i[i+2][lane] + bb.w * sT_i[i+3][lane];
            }
            s *= scale;
            if (k0 + lane > row) s = -INFINITY;
            float cm = s;
#pragma unroll
            for (int off = 16; off; off >>= 1)
                cm = fmaxf(cm, __shfl_xor_sync(0xffffffffu, cm, off));
            float mnew = fmaxf(m, cm);
            p = expf(s - mnew);
            float corr = expf(m - mnew);
            float ps = p;
#pragma unroll
            for (int off = 16; off; off >>= 1)
                ps += __shfl_xor_sync(0xffffffffu, ps, off);
            l = l * corr + ps;
#pragma unroll
            for (int i = 0; i < 4; i++) { o_r[i] *= corr; o_i[i] *= corr; }
            m = mnew;
        }
        __syncthreads();
#pragma unroll
        for (int i = 0; i < 16; i++) {
            int e = tid + (i << 8);
            int key = e >> 7, d = e & 127;
            size_t g = kvbase + (size_t)(k0 + key) * NKV + d;
            sT_r[d][key] = g_v_re[g];
            sT_i[d][key] = g_v_im[g];
        }
        __syncthreads();
        if (k0 <= row) {
#pragma unroll 8
            for (int j = 0; j < 32; j++) {
                float pj = __shfl_sync(0xffffffffu, p, j);
#pragma unroll
                for (int i = 0; i < 4; i++) {
                    o_r[i] += pj * sT_r[lane + (i << 5)][j];
                    o_i[i] += pj * sT_i[lane + (i << 5)][j];
                }
            }
        }
    }
    float invl = 1.f / l;
#pragma unroll
    for (int i = 0; i < 4; i++) {
        g_o_re[qoff + lane + (i << 5)] = o_r[i] * invl;
        g_o_im[qoff + lane + (i << 5)] = o_i[i] * invl;
    }
}

// ---------------- launch (R3 order) ----------------
extern "C" void kernel_launch(void* const* d_in, const int* in_sizes, int n_in,
                              void* d_out, int out_size) {
    const float* hr  = (const float*)d_in[0];
    const float* hi  = (const float*)d_in[1];
    const float* wqr = (const float*)d_in[2];
    const float* wqi = (const float*)d_in[3];
    const float* wkr = (const float*)d_in[4];
    const float* wki = (const float*)d_in[5];
    const float* wvr = (const float*)d_in[6];
    const float* wvi = (const float*)d_in[7];
    const float* wor = (const float*)d_in[8];
    const float* woi = (const float*)d_in[9];
    float* out = (float*)d_out;

    mag_partial<<<256, 256>>>(wqr, wqi, D_ * NQ, 0);
    mag_partial<<<256, 256>>>(wkr, wki, D_ * NKV, 1);
    mag_partial<<<256, 256>>>(wvr, wvi, D_ * NKV, 2);
    mag_partial<<<256, 256>>>(wor, woi, NQ * D_, 3);
    mag_final<<<1, 32>>>();

    dim3 tb(32, 8);
    tern_T<<<dim3(NQ / 32, D_ / 32), tb>>>(wqr, wqi, 0, D_, NQ);
    tern_T<<<dim3(NKV / 32, D_ / 32), tb>>>(wkr, wki, 1, D_, NKV);
    tern_T<<<dim3(NKV / 32, D_ / 32), tb>>>(wvr, wvi, 2, D_, NKV);
    tern_T<<<dim3(D_ / 32, NQ / 32), tb>>>(wor, woi, 3, NQ, D_);

    act_quant_k<<<MTOK, 256>>>(hr, hi, 0);

    gemm_cplx_wmma<<<dim3(NQ / 64, MTOK / 64), 128>>>(0, nullptr, nullptr);
    gemm_cplx_wmma<<<dim3(NKV / 64, MTOK / 64), 128>>>(1, nullptr, nullptr);
    gemm_cplx_wmma<<<dim3(NKV / 64, MTOK / 64), 128>>>(2, nullptr, nullptr);

    rope_k<<<(MTOK * H_ * 64) / 256, 256>>>(0);
    rope_k<<<(MTOK * KV_ * 64) / 256, 256>>>(1);

    attn_k<<<dim3(S_ / 8, B_ * H_), 256>>>();

    act_quant_k<<<MTOK, 256>>>(nullptr, nullptr, 1);

    gemm_cplx_wmma<<<dim3(NQ / 64, MTOK / 64), 128>>>(3, out, out + (size_t)B_ * S_ * D_);
}

// round 12
// speedup vs baseline: 1.4531x; 1.2371x over previous
#include <cuda_runtime.h>
#include <cuda_fp16.h>
#include <mma.h>
#include <math.h>
#include <stdint.h>

using namespace nvcuda;

#define B_   2
#define S_   1024
#define D_   2048
#define H_   16
#define KV_  4
#define HD_  128
#define MTOK 2048      // B*S tokens
#define NQ   2048      // H*HD
#define NKV  512       // KV*HD
#define KDIM 2048

// ---------------- scratch (static __device__, no allocs) ----------------
// activations: re/im/sum planes, f16 ints
__device__ __align__(16) __half g_xhr[MTOK*D_], g_xhi[MTOK*D_], g_xhs[MTOK*D_];
__device__ float  g_xscale[MTOK];
__device__ __align__(16) __half g_ohr[MTOK*NQ], g_ohi[MTOK*NQ], g_ohs[MTOK*NQ];
__device__ float  g_oscale[MTOK];

// ternary f16 weights, [N][K] K-contiguous, re/im/sum planes
__device__ __align__(16) __half g_wq_r[NQ*D_],  g_wq_i[NQ*D_],  g_wq_s[NQ*D_];
__device__ __align__(16) __half g_wk_r[NKV*D_], g_wk_i[NKV*D_], g_wk_s[NKV*D_];
__device__ __align__(16) __half g_wv_r[NKV*D_], g_wv_i[NKV*D_], g_wv_s[NKV*D_];
__device__ __align__(16) __half g_wo_r[D_*NQ],  g_wo_i[D_*NQ],  g_wo_s[D_*NQ];

__device__ float g_mag[4];
__device__ float g_part2[4][4096];

__device__ float g_q_re[MTOK*NQ],  g_q_im[MTOK*NQ];
__device__ float g_k_re[MTOK*NKV], g_k_im[MTOK*NKV];
__device__ float g_v_re[MTOK*NKV], g_v_im[MTOK*NKV];
__device__ float g_o_re[MTOK*NQ],  g_o_im[MTOK*NQ];

// ---------------- ternarize + transpose + fused mag partial ----------------
__global__ void tern_T(const float* __restrict__ wr, const float* __restrict__ wi,
                       int sel, int K, int N) {
    __half *dr, *di, *ds;
    if (sel == 0)      { dr = g_wq_r; di = g_wq_i; ds = g_wq_s; }
    else if (sel == 1) { dr = g_wk_r; di = g_wk_i; ds = g_wk_s; }
    else if (sel == 2) { dr = g_wv_r; di = g_wv_i; ds = g_wv_s; }
    else               { dr = g_wo_r; di = g_wo_i; ds = g_wo_s; }
    __shared__ float tr[32][33], ti[32][33];
    __shared__ float red[256];
    int n0 = blockIdx.x * 32, k0 = blockIdx.y * 32;
    float msum = 0.f;
#pragma unroll
    for (int j = 0; j < 4; j++) {
        int k = k0 + threadIdx.y + 8 * j;
        float a = wr[(size_t)k * N + n0 + threadIdx.x];
        float b = wi[(size_t)k * N + n0 + threadIdx.x];
        tr[threadIdx.y + 8 * j][threadIdx.x] = a;
        ti[threadIdx.y + 8 * j][threadIdx.x] = b;
        msum += sqrtf(a * a + b * b);
    }
    int t = threadIdx.y * 32 + threadIdx.x;
    red[t] = msum;
    __syncthreads();
    for (int st = 128; st > 0; st >>= 1) {
        if (t < st) red[t] += red[t + st];
        __syncthreads();
    }
    if (t == 0) g_part2[sel][blockIdx.y * gridDim.x + blockIdx.x] = red[0];
#pragma unroll
    for (int j = 0; j < 4; j++) {
        int n = n0 + threadIdx.y + 8 * j;
        int k = k0 + threadIdx.x;
        float a = tr[threadIdx.x][threadIdx.y + 8 * j];
        float b = ti[threadIdx.x][threadIdx.y + 8 * j];
        float r = 0.f, m = 0.f;
        if (fabsf(a) >= fabsf(b)) r = (a > 0.f) ? 1.f : ((a < 0.f) ? -1.f : 0.f);
        else                      m = (b > 0.f) ? 1.f : ((b < 0.f) ? -1.f : 0.f);
        size_t idx = (size_t)n * K + k;
        dr[idx] = __float2half_rn(r);
        di[idx] = __float2half_rn(m);
        ds[idx] = __float2half_rn(r + m);
    }
}

__global__ void mag_final2() {
    int slot = blockIdx.x;
    int n = (slot == 0 || slot == 3) ? 4096 : 1024;
    __shared__ float red[256];
    float s = 0.f;
    for (int i = threadIdx.x; i < n; i += 256) s += g_part2[slot][i];
    red[threadIdx.x] = s;
    __syncthreads();
    for (int st = 128; st > 0; st >>= 1) {
        if (threadIdx.x < st) red[threadIdx.x] += red[threadIdx.x + st];
        __syncthreads();
    }
    if (threadIdx.x == 0) {
        const float cnt[4] = {4194304.f, 1048576.f, 1048576.f, 4194304.f};
        g_mag[slot] = red[0] / cnt[slot];
    }
}

// ---------------- per-token activation quantization (re/im/sum f16) ----------------
__global__ void act_quant_k(const float* __restrict__ xr_in,
                            const float* __restrict__ xi_in, int sel) {
    const float *xr, *xi; __half *qr, *qi, *qs; float* sc;
    if (sel == 0) { xr = xr_in;  xi = xi_in;  qr = g_xhr; qi = g_xhi; qs = g_xhs; sc = g_xscale; }
    else          { xr = g_o_re; xi = g_o_im; qr = g_ohr; qi = g_ohi; qs = g_ohs; sc = g_oscale; }
    const int K = 2048;
    int t = blockIdx.x;
    size_t base = (size_t)t * K;
    __shared__ float red[256];
    __shared__ float s_sh;
    float mx = 0.f;
    for (int i = threadIdx.x; i < K; i += 256)
        mx = fmaxf(mx, fmaxf(fabsf(xr[base + i]), fabsf(xi[base + i])));
    red[threadIdx.x] = mx;
    __syncthreads();
    for (int st = 128; st > 0; st >>= 1) {
        if (threadIdx.x < st) red[threadIdx.x] = fmaxf(red[threadIdx.x], red[threadIdx.x + st]);
        __syncthreads();
    }
    if (threadIdx.x == 0) {
        float s = 127.f / fmaxf(red[0], 1e-5f);
        s_sh = s;
        sc[t] = 1.f / s;
    }
    __syncthreads();
    float s = s_sh;
    for (int i = threadIdx.x; i < K; i += 256) {
        float vr = rintf(xr[base + i] * s); vr = fminf(fmaxf(vr, -128.f), 127.f);
        float vi = rintf(xi[base + i] * s); vi = fminf(fmaxf(vi, -128.f), 127.f);
        qr[base + i] = __float2half_rn(vr);       // exact ints
        qi[base + i] = __float2half_rn(vi);
        qs[base + i] = __float2half_rn(vr + vi);  // <=254, exact in f16
    }
}

// ---------------- complex WMMA GEMM, Karatsuba (3 mma per 16x16x16 frag) ----------
// t1 = Ar.Br, t2 = Ai.Bi, t3 = As.Bs;  Re = t1-t2, Im = t3-t1-t2  (all exact ints)
#define SWK 56   // smem row stride in halfs (112B, 16B-aligned, conflict-free ldmatrix)
__global__ void __launch_bounds__(128) gemm_cplx_wmma(int sel,
                                                      float* __restrict__ outr_p,
                                                      float* __restrict__ outi_p) {
    const __half *Ar, *Ai, *As, *Br, *Bi, *Bs; const float* ts; float *Or, *Oi; int N;
    if (sel == 0)      { Ar=g_xhr; Ai=g_xhi; As=g_xhs; Br=g_wq_r; Bi=g_wq_i; Bs=g_wq_s; ts=g_xscale; Or=g_q_re; Oi=g_q_im; N=NQ;  }
    else if (sel == 1) { Ar=g_xhr; Ai=g_xhi; As=g_xhs; Br=g_wk_r; Bi=g_wk_i; Bs=g_wk_s; ts=g_xscale; Or=g_k_re; Oi=g_k_im; N=NKV; }
    else if (sel == 2) { Ar=g_xhr; Ai=g_xhi; As=g_xhs; Br=g_wv_r; Bi=g_wv_i; Bs=g_wv_s; ts=g_xscale; Or=g_v_re; Oi=g_v_im; N=NKV; }
    else               { Ar=g_ohr; Ai=g_ohi; As=g_ohs; Br=g_wo_r; Bi=g_wo_i; Bs=g_wo_s; ts=g_oscale; Or=outr_p; Oi=outi_p; N=NQ;  }
    __shared__ __align__(16) __half pool[6][64][SWK];   // Ar Ai As Br Bi Bs tiles
    int tid = threadIdx.x, lane = tid & 31, wid = tid >> 5;
    int wm = wid >> 1, wn = wid & 1;
    int m0 = blockIdx.y << 6, n0 = blockIdx.x << 6;

    wmma::fragment<wmma::matrix_a, 16, 16, 16, __half, wmma::row_major> fa[3][2];
    wmma::fragment<wmma::matrix_b, 16, 16, 16, __half, wmma::col_major> fb[3][2];
    wmma::fragment<wmma::accumulator, 16, 16, 16, float> fc[3][2][2];
#pragma unroll
    for (int p = 0; p < 3; p++)
#pragma unroll
        for (int a = 0; a < 2; a++)
#pragma unroll
            for (int b = 0; b < 2; b++)
                wmma::fill_fragment(fc[p][a][b], 0.0f);

    int r_ld = tid >> 1;
    int hh = (tid & 1) << 4;                   // half offset 0 or 16
    const __half* gp[6];
    gp[0] = Ar + (size_t)(m0 + r_ld) * KDIM;
    gp[1] = Ai + (size_t)(m0 + r_ld) * KDIM;
    gp[2] = As + (size_t)(m0 + r_ld) * KDIM;
    gp[3] = Br + (size_t)(n0 + r_ld) * KDIM;
    gp[4] = Bi + (size_t)(n0 + r_ld) * KDIM;
    gp[5] = Bs + (size_t)(n0 + r_ld) * KDIM;
    int4 rv[6][2];
#pragma unroll
    for (int p = 0; p < 6; p++) {
        const int4* q = (const int4*)(gp[p] + hh);
        rv[p][0] = q[0]; rv[p][1] = q[1];
    }

    const int NS = KDIM / 32;                  // 64 stages
    for (int s = 0; s < NS; s++) {
        __syncthreads();                       // WAR: previous compute done
#pragma unroll
        for (int p = 0; p < 6; p++) {
            *(int4*)&pool[p][r_ld][hh]     = rv[p][0];
            *(int4*)&pool[p][r_ld][hh + 8] = rv[p][1];
        }
        __syncthreads();                       // RAW: tiles visible
        if (s + 1 < NS) {
            size_t kc = (size_t)(s + 1) << 5;
#pragma unroll
            for (int p = 0; p < 6; p++) {
                const int4* q = (const int4*)(gp[p] + kc + hh);
                rv[p][0] = q[0]; rv[p][1] = q[1];
            }
        }
#pragma unroll
        for (int k = 0; k < 2; k++) {
            int kh = k << 4;
#pragma unroll
            for (int p = 0; p < 3; p++) {
#pragma unroll
                for (int mi = 0; mi < 2; mi++)
                    wmma::load_matrix_sync(fa[p][mi], &pool[p][(wm << 5) + (mi << 4)][kh], SWK);
#pragma unroll
                for (int ni = 0; ni < 2; ni++)
                    wmma::load_matrix_sync(fb[p][ni], &pool[3 + p][(wn << 5) + (ni << 4)][kh], SWK);
            }
#pragma unroll
            for (int p = 0; p < 3; p++)
#pragma unroll
                for (int mi = 0; mi < 2; mi++)
#pragma unroll
                    for (int ni = 0; ni < 2; ni++)
                        wmma::mma_sync(fc[p][mi][ni], fa[p][mi], fb[p][ni], fc[p][mi][ni]);
        }
    }

    // ---------------- epilogue ----------------
    __syncthreads();
    float* sC = (float*)&pool[0][0][0] + wid * 256;   // 1KB per warp
    float mg = g_mag[sel];
    int r = lane >> 1, c0 = (lane & 1) << 3;
#pragma unroll
    for (int mi = 0; mi < 2; mi++) {
#pragma unroll
        for (int ni = 0; ni < 2; ni++) {
            int grow = m0 + (wm << 5) + (mi << 4) + r;
            int gcol = n0 + (wn << 5) + (ni << 4) + c0;
            float sc = mg * ts[grow];
            size_t gb = (size_t)grow * N + gcol;
            const float* src = sC + r * 16 + c0;
            float t1[8], t2[8], t3[8];

            wmma::store_matrix_sync(sC, fc[0][mi][ni], 16, wmma::mem_row_major);
            __syncwarp();
#pragma unroll
            for (int e = 0; e < 8; e++) t1[e] = src[e];
            __syncwarp();
            wmma::store_matrix_sync(sC, fc[1][mi][ni], 16, wmma::mem_row_major);
            __syncwarp();
#pragma unroll
            for (int e = 0; e < 8; e++) t2[e] = src[e];
            __syncwarp();
            wmma::store_matrix_sync(sC, fc[2][mi][ni], 16, wmma::mem_row_major);
            __syncwarp();
#pragma unroll
            for (int e = 0; e < 8; e++) t3[e] = src[e];
            __syncwarp();

            float4 o1, o2;
            o1.x = (t1[0]-t2[0])*sc; o1.y = (t1[1]-t2[1])*sc;
            o1.z = (t1[2]-t2[2])*sc; o1.w = (t1[3]-t2[3])*sc;
            o2.x = (t1[4]-t2[4])*sc; o2.y = (t1[5]-t2[5])*sc;
            o2.z = (t1[6]-t2[6])*sc; o2.w = (t1[7]-t2[7])*sc;
            *(float4*)(Or + gb)     = o1;
            *(float4*)(Or + gb + 4) = o2;
            o1.x = (t3[0]-t1[0]-t2[0])*sc; o1.y = (t3[1]-t1[1]-t2[1])*sc;
            o1.z = (t3[2]-t1[2]-t2[2])*sc; o1.w = (t3[3]-t1[3]-t2[3])*sc;
            o2.x = (t3[4]-t1[4]-t2[4])*sc; o2.y = (t3[5]-t1[5]-t2[5])*sc;
            o2.z = (t3[6]-t1[6]-t2[6])*sc; o2.w = (t3[7]-t1[7]-t2[7])*sc;
            *(float4*)(Oi + gb)     = o1;
            *(float4*)(Oi + gb + 4) = o2;
        }
    }
}

// ---------------- RoPE (R3 verbatim) ----------------
__global__ void rope_k(int sel) {
    float* x; int nh;
    if (sel == 0) { x = g_q_re; nh = H_; } else { x = g_k_re; nh = KV_; }
    int total = MTOK * nh * 64;
    int idx = blockIdx.x * blockDim.x + threadIdx.x;
    if (idx >= total) return;
    int d = idx & 63;
    int th = idx >> 6;
    int head = th % nh;
    int tok = th / nh;
    int pos = tok & (S_ - 1);
    float inv = (float)exp(-log(10000.0) * (double)d / 64.0);
    float ang = (float)pos * inv;
    float c = cosf(ang), sn = sinf(ang);
    size_t off = (size_t)tok * (nh * HD_) + head * HD_;
    float x0 = x[off + d], x1 = x[off + d + 64];
    x[off + d]      = x0 * c - x1 * sn;
    x[off + d + 64] = x1 * c + x0 * sn;
}

// ---------------- causal attention: fp32, 2 q-rows per warp ----------------
// grid (S/16, B*H), 256 thr (8 warps x 2 rows); dyn smem 50176B
#define ATTN_SMEM 50176
__global__ void __launch_bounds__(256) attn_k() {
    extern __shared__ float dyn[];
    float* sq_r = dyn;                  // [16][128]
    float* sq_i = dyn + 2048;
    float* sK_r = dyn + 4096;           // [32][132] (K then V)
    float* sK_i = dyn + 4096 + 4224;
    int tid = threadIdx.x;
    int lane = tid & 31, w = tid >> 5;
    int b = blockIdx.y >> 4, h = blockIdx.y & 15;
    int kvh = h >> 2;
    int row0g = blockIdx.x << 4;
    int rl0 = w << 1, rl1 = rl0 + 1;
    int r0 = row0g + rl0, r1 = r0 + 1;
    size_t qbase = ((size_t)(b * S_ + row0g)) * NQ + h * HD_;
    for (int i = tid; i < 16 * 128; i += 256) {
        int rl = i >> 7, d = i & 127;
        size_t g = qbase + (size_t)rl * NQ + d;
        sq_r[i] = g_q_re[g];
        sq_i[i] = g_q_im[g];
    }
    float m0 = -INFINITY, l0 = 0.f, m1 = -INFINITY, l1 = 0.f;
    float o0r[4] = {0,0,0,0}, o0i[4] = {0,0,0,0};
    float o1r[4] = {0,0,0,0}, o1i[4] = {0,0,0,0};
    const float scale = 0.08838834764831845f;   // 1/sqrt(128)
    int nch = ((row0g + 15) >> 5) + 1;
    size_t kvbase = (size_t)(b * S_) * NKV + kvh * HD_;
    float p0 = 0.f, p1 = 0.f;
    for (int c = 0; c < nch; c++) {
        int k0 = c << 5;
        __syncthreads();
#pragma unroll
        for (int i = 0; i < 16; i++) {          // K tile [key][d]
            int e = tid + (i << 8);
            int key = e >> 7, d = e & 127;
            size_t g = kvbase + (size_t)(k0 + key) * NKV + d;
            sK_r[key * 132 + d] = g_k_re[g];
            sK_i[key * 132 + d] = g_k_im[g];
        }
        __syncthreads();
        bool act = (k0 <= r0);                  // warp-uniform (r0 even, k0 mult of 32)
        p0 = 0.f; p1 = 0.f;
        if (act) {
            float s0 = 0.f, s1 = 0.f;
            const float4* kr4 = (const float4*)(sK_r + lane * 132);
            const float4* ki4 = (const float4*)(sK_i + lane * 132);
            const float4* q0r = (const float4*)(sq_r + rl0 * 128);
            const float4* q0i = (const float4*)(sq_i + rl0 * 128);
            const float4* q1r = (const float4*)(sq_r + rl1 * 128);
            const float4* q1i = (const float4*)(sq_i + rl1 * 128);
#pragma unroll 8
            for (int i4 = 0; i4 < 32; i4++) {
                float4 kr = kr4[i4], ki = ki4[i4];
                float4 a;
                a = q0r[i4]; s0 += a.x*kr.x + a.y*kr.y + a.z*kr.z + a.w*kr.w;
                a = q0i[i4]; s0 += a.x*ki.x + a.y*ki.y + a.z*ki.z + a.w*ki.w;
                a = q1r[i4]; s1 += a.x*kr.x + a.y*kr.y + a.z*kr.z + a.w*kr.w;
                a = q1i[i4]; s1 += a.x*ki.x + a.y*ki.y + a.z*ki.z + a.w*ki.w;
            }
            s0 *= scale; s1 *= scale;
            if (k0 + lane > r0) s0 = -INFINITY;
            if (k0 + lane > r1) s1 = -INFINITY;
            // online softmax row0
            float cm = s0;
#pragma unroll
            for (int off = 16; off; off >>= 1)
                cm = fmaxf(cm, __shfl_xor_sync(0xffffffffu, cm, off));
            float mnew = fmaxf(m0, cm);
            p0 = expf(s0 - mnew);
            float corr = expf(m0 - mnew);
            float ps = p0;
#pragma unroll
            for (int off = 16; off; off >>= 1)
                ps += __shfl_xor_sync(0xffffffffu, ps, off);
            l0 = l0 * corr + ps;
#pragma unroll
            for (int i = 0; i < 4; i++) { o0r[i] *= corr; o0i[i] *= corr; }
            m0 = mnew;
            // online softmax row1
            cm = s1;
#pragma unroll
            for (int off = 16; off; off >>= 1)
                cm = fmaxf(cm, __shfl_xor_sync(0xffffffffu, cm, off));
            mnew = fmaxf(m1, cm);
            p1 = expf(s1 - mnew);
            corr = expf(m1 - mnew);
            ps = p1;
#pragma unroll
            for (int off = 16; off; off >>= 1)
                ps += __shfl_xor_sync(0xffffffffu, ps, off);
            l1 = l1 * corr + ps;
#pragma unroll
            for (int i = 0; i < 4; i++) { o1r[i] *= corr; o1i[i] *= corr; }
            m1 = mnew;
        }
        __syncthreads();
#pragma unroll
        for (int i = 0; i < 16; i++) {          // V tile (overwrite K buffer)
            int e = tid + (i << 8);
            int key = e >> 7, d = e & 127;
            size_t g = kvbase + (size_t)(k0 + key) * NKV + d;
            sK_r[key * 132 + d] = g_v_re[g];
            sK_i[key * 132 + d] = g_v_im[g];
        }
        __syncthreads();
        if (act) {
#pragma unroll 8
            for (int j = 0; j < 32; j++) {
                float pj0 = __shfl_sync(0xffffffffu, p0, j);
                float pj1 = __shfl_sync(0xffffffffu, p1, j);
                const float* vr = sK_r + j * 132 + lane;
                const float* vi = sK_i + j * 132 + lane;
#pragma unroll
                for (int i = 0; i < 4; i++) {
                    float vre = vr[i << 5], vim = vi[i << 5];
                    o0r[i] += pj0 * vre; o0i[i] += pj0 * vim;
                    o1r[i] += pj1 * vre; o1i[i] += pj1 * vim;
                }
            }
        }
    }
    float inv0 = 1.f / l0, inv1 = 1.f / l1;
    size_t q0off = qbase + (size_t)rl0 * NQ;
    size_t q1off = qbase + (size_t)rl1 * NQ;
#pragma unroll
    for (int i = 0; i < 4; i++) {
        g_o_re[q0off + lane + (i << 5)] = o0r[i] * inv0;
        g_o_im[q0off + lane + (i << 5)] = o0i[i] * inv0;
        g_o_re[q1off + lane + (i << 5)] = o1r[i] * inv1;
        g_o_im[q1off + lane + (i << 5)] = o1i[i] * inv1;
    }
}

// ---------------- launch ----------------
extern "C" void kernel_launch(void* const* d_in, const int* in_sizes, int n_in,
                              void* d_out, int out_size) {
    const float* hr  = (const float*)d_in[0];
    const float* hi  = (const float*)d_in[1];
    const float* wqr = (const float*)d_in[2];
    const float* wqi = (const float*)d_in[3];
    const float* wkr = (const float*)d_in[4];
    const float* wki = (const float*)d_in[5];
    const float* wvr = (const float*)d_in[6];
    const float* wvi = (const float*)d_in[7];
    const float* wor = (const float*)d_in[8];
    const float* woi = (const float*)d_in[9];
    float* out = (float*)d_out;

    cudaFuncSetAttribute(attn_k, cudaFuncAttributeMaxDynamicSharedMemorySize, ATTN_SMEM);

    dim3 tb(32, 8);
    tern_T<<<dim3(NQ / 32, D_ / 32), tb>>>(wqr, wqi, 0, D_, NQ);
    tern_T<<<dim3(NKV / 32, D_ / 32), tb>>>(wkr, wki, 1, D_, NKV);
    tern_T<<<dim3(NKV / 32, D_ / 32), tb>>>(wvr, wvi, 2, D_, NKV);
    tern_T<<<dim3(D_ / 32, NQ / 32), tb>>>(wor, woi, 3, NQ, D_);
    mag_final2<<<4, 256>>>();

    act_quant_k<<<MTOK, 256>>>(hr, hi, 0);

    gemm_cplx_wmma<<<dim3(NQ / 64, MTOK / 64), 128>>>(0, nullptr, nullptr);
    gemm_cplx_wmma<<<dim3(NKV / 64, MTOK / 64), 128>>>(1, nullptr, nullptr);
    gemm_cplx_wmma<<<dim3(NKV / 64, MTOK / 64), 128>>>(2, nullptr, nullptr);

    rope_k<<<(MTOK * H_ * 64) / 256, 256>>>(0);
    rope_k<<<(MTOK * KV_ * 64) / 256, 256>>>(1);

    attn_k<<<dim3(S_ / 16, B_ * H_), 256, ATTN_SMEM>>>();

    act_quant_k<<<MTOK, 256>>>(nullptr, nullptr, 1);

    gemm_cplx_wmma<<<dim3(NQ / 64, MTOK / 64), 128>>>(3, out, out + (size_t)B_ * S_ * D_);
}

// round 17
// speedup vs baseline: 1.4640x; 1.0075x over previous
#include <cuda_runtime.h>
#include <cuda_fp16.h>
#include <mma.h>
#include <math.h>
#include <stdint.h>

using namespace nvcuda;

#define B_   2
#define S_   1024
#define D_   2048
#define H_   16
#define KV_  4
#define HD_  128
#define MTOK 2048      // B*S tokens
#define NQ   2048      // H*HD
#define NKV  512       // KV*HD
#define KDIM 2048

// ---------------- scratch (static __device__, no allocs) ----------------
// activations: re/im/sum planes, f16 ints
__device__ __align__(16) __half g_xhr[MTOK*D_], g_xhi[MTOK*D_], g_xhs[MTOK*D_];
__device__ float  g_xscale[MTOK];
__device__ __align__(16) __half g_ohr[MTOK*NQ], g_ohi[MTOK*NQ], g_ohs[MTOK*NQ];
__device__ float  g_oscale[MTOK];

// ternary f16 weights, [N][K] K-contiguous, re/im/sum planes
__device__ __align__(16) __half g_wq_r[NQ*D_],  g_wq_i[NQ*D_],  g_wq_s[NQ*D_];
__device__ __align__(16) __half g_wk_r[NKV*D_], g_wk_i[NKV*D_], g_wk_s[NKV*D_];
__device__ __align__(16) __half g_wv_r[NKV*D_], g_wv_i[NKV*D_], g_wv_s[NKV*D_];
__device__ __align__(16) __half g_wo_r[D_*NQ],  g_wo_i[D_*NQ],  g_wo_s[D_*NQ];

__device__ float g_mag[4];
__device__ float g_part2[4][4096];

// interleaved (re,im) activations for attention phase
__device__ __align__(16) float g_q2[MTOK*NQ*2];
__device__ __align__(16) float g_k2[MTOK*NKV*2];
__device__ __align__(16) float g_v2[MTOK*NKV*2];
__device__ __align__(16) float g_o2[MTOK*NQ*2];

// ---------------- packed f32x2 helpers ----------------
#define FMA2(o, a, b) asm("fma.rn.f32x2 %0, %1, %2, %0;" : "+l"(o) : "l"(a), "l"(b))
#define MUL2(o, a)    asm("mul.rn.f32x2 %0, %0, %1;"     : "+l"(o) : "l"(a))
__device__ __forceinline__ unsigned long long pk2(float lo, float hi) {
    unsigned long long r;
    asm("mov.b64 %0, {%1, %2};" : "=l"(r) : "f"(lo), "f"(hi));
    return r;
}
__device__ __forceinline__ void upk2(float& lo, float& hi, unsigned long long v) {
    asm("mov.b64 {%0, %1}, %2;" : "=f"(lo), "=f"(hi) : "l"(v));
}

// ---------------- ternarize + transpose + fused mag partial ----------------
__global__ void tern_T(const float* __restrict__ wr, const float* __restrict__ wi,
                       int sel, int K, int N) {
    __half *dr, *di, *ds;
    if (sel == 0)      { dr = g_wq_r; di = g_wq_i; ds = g_wq_s; }
    else if (sel == 1) { dr = g_wk_r; di = g_wk_i; ds = g_wk_s; }
    else if (sel == 2) { dr = g_wv_r; di = g_wv_i; ds = g_wv_s; }
    else               { dr = g_wo_r; di = g_wo_i; ds = g_wo_s; }
    __shared__ float tr[32][33], ti[32][33];
    __shared__ float red[256];
    int n0 = blockIdx.x * 32, k0 = blockIdx.y * 32;
    float msum = 0.f;
#pragma unroll
    for (int j = 0; j < 4; j++) {
        int k = k0 + threadIdx.y + 8 * j;
        float a = wr[(size_t)k * N + n0 + threadIdx.x];
        float b = wi[(size_t)k * N + n0 + threadIdx.x];
        tr[threadIdx.y + 8 * j][threadIdx.x] = a;
        ti[threadIdx.y + 8 * j][threadIdx.x] = b;
        msum += sqrtf(a * a + b * b);
    }
    int t = threadIdx.y * 32 + threadIdx.x;
    red[t] = msum;
    __syncthreads();
    for (int st = 128; st > 0; st >>= 1) {
        if (t < st) red[t] += red[t + st];
        __syncthreads();
    }
    if (t == 0) g_part2[sel][blockIdx.y * gridDim.x + blockIdx.x] = red[0];
#pragma unroll
    for (int j = 0; j < 4; j++) {
        int n = n0 + threadIdx.y + 8 * j;
        int k = k0 + threadIdx.x;
        float a = tr[threadIdx.x][threadIdx.y + 8 * j];
        float b = ti[threadIdx.x][threadIdx.y + 8 * j];
        float r = 0.f, m = 0.f;
        if (fabsf(a) >= fabsf(b)) r = (a > 0.f) ? 1.f : ((a < 0.f) ? -1.f : 0.f);
        else                      m = (b > 0.f) ? 1.f : ((b < 0.f) ? -1.f : 0.f);
        size_t idx = (size_t)n * K + k;
        dr[idx] = __float2half_rn(r);
        di[idx] = __float2half_rn(m);
        ds[idx] = __float2half_rn(r + m);
    }
}

__global__ void mag_final2() {
    int slot = blockIdx.x;
    int n = (slot == 0 || slot == 3) ? 4096 : 1024;
    __shared__ float red[256];
    float s = 0.f;
    for (int i = threadIdx.x; i < n; i += 256) s += g_part2[slot][i];
    red[threadIdx.x] = s;
    __syncthreads();
    for (int st = 128; st > 0; st >>= 1) {
        if (threadIdx.x < st) red[threadIdx.x] += red[threadIdx.x + st];
        __syncthreads();
    }
    if (threadIdx.x == 0) {
        const float cnt[4] = {4194304.f, 1048576.f, 1048576.f, 4194304.f};
        g_mag[slot] = red[0] / cnt[slot];
    }
}

// ---------------- per-token activation quantization (re/im/sum f16) ----------------
// sel 0: planar fp32 inputs; sel 1: interleaved g_o2
__global__ void act_quant_k(const float* __restrict__ xr_in,
                            const float* __restrict__ xi_in, int sel) {
    __half *qr, *qi, *qs; float* sc;
    if (sel == 0) { qr = g_xhr; qi = g_xhi; qs = g_xhs; sc = g_xscale; }
    else          { qr = g_ohr; qi = g_ohi; qs = g_ohs; sc = g_oscale; }
    const int K = 2048;
    int t = blockIdx.x;
    size_t base = (size_t)t * K;
    __shared__ float red[256];
    __shared__ float s_sh;
    float mx = 0.f;
    if (sel == 0) {
        for (int i = threadIdx.x; i < K; i += 256)
            mx = fmaxf(mx, fmaxf(fabsf(xr_in[base + i]), fabsf(xi_in[base + i])));
    } else {
        const float2* o2 = (const float2*)g_o2;
        for (int i = threadIdx.x; i < K; i += 256) {
            float2 v = o2[base + i];
            mx = fmaxf(mx, fmaxf(fabsf(v.x), fabsf(v.y)));
        }
    }
    red[threadIdx.x] = mx;
    __syncthreads();
    for (int st = 128; st > 0; st >>= 1) {
        if (threadIdx.x < st) red[threadIdx.x] = fmaxf(red[threadIdx.x], red[threadIdx.x + st]);
        __syncthreads();
    }
    if (threadIdx.x == 0) {
        float s = 127.f / fmaxf(red[0], 1e-5f);
        s_sh = s;
        sc[t] = 1.f / s;
    }
    __syncthreads();
    float s = s_sh;
    for (int i = threadIdx.x; i < K; i += 256) {
        float xrv, xiv;
        if (sel == 0) { xrv = xr_in[base + i]; xiv = xi_in[base + i]; }
        else { float2 v = ((const float2*)g_o2)[base + i]; xrv = v.x; xiv = v.y; }
        float vr = rintf(xrv * s); vr = fminf(fmaxf(vr, -128.f), 127.f);
        float vi = rintf(xiv * s); vi = fminf(fmaxf(vi, -128.f), 127.f);
        qr[base + i] = __float2half_rn(vr);       // exact ints
        qi[base + i] = __float2half_rn(vi);
        qs[base + i] = __float2half_rn(vr + vi);  // <=254, exact in f16
    }
}

// ---------------- complex WMMA GEMM, Karatsuba (3 mma per 16x16x16 frag) ----------
// t1 = Ar.Br, t2 = Ai.Bi, t3 = As.Bs;  Re = t1-t2, Im = t3-t1-t2  (all exact ints)
// sel 0-2: write interleaved (re,im) float2;  sel 3: planar to harness output
#define SWK 56   // smem row stride in halfs (112B, 16B-aligned, conflict-free ldmatrix)
__global__ void __launch_bounds__(128) gemm_cplx_wmma(int sel,
                                                      float* __restrict__ outr_p,
                                                      float* __restrict__ outi_p) {
    const __half *Ar, *Ai, *As, *Br, *Bi, *Bs; const float* ts; int N;
    float* dst2 = nullptr;
    if (sel == 0)      { Ar=g_xhr; Ai=g_xhi; As=g_xhs; Br=g_wq_r; Bi=g_wq_i; Bs=g_wq_s; ts=g_xscale; dst2=g_q2; N=NQ;  }
    else if (sel == 1) { Ar=g_xhr; Ai=g_xhi; As=g_xhs; Br=g_wk_r; Bi=g_wk_i; Bs=g_wk_s; ts=g_xscale; dst2=g_k2; N=NKV; }
    else if (sel == 2) { Ar=g_xhr; Ai=g_xhi; As=g_xhs; Br=g_wv_r; Bi=g_wv_i; Bs=g_wv_s; ts=g_xscale; dst2=g_v2; N=NKV; }
    else               { Ar=g_ohr; Ai=g_ohi; As=g_ohs; Br=g_wo_r; Bi=g_wo_i; Bs=g_wo_s; ts=g_oscale; N=NQ;  }
    __shared__ __align__(16) __half pool[6][64][SWK];   // Ar Ai As Br Bi Bs tiles
    int tid = threadIdx.x, lane = tid & 31, wid = tid >> 5;
    int wm = wid >> 1, wn = wid & 1;
    int m0 = blockIdx.y << 6, n0 = blockIdx.x << 6;

    wmma::fragment<wmma::matrix_a, 16, 16, 16, __half, wmma::row_major> fa[3][2];
    wmma::fragment<wmma::matrix_b, 16, 16, 16, __half, wmma::col_major> fb[3][2];
    wmma::fragment<wmma::accumulator, 16, 16, 16, float> fc[3][2][2];
#pragma unroll
    for (int p = 0; p < 3; p++)
#pragma unroll
        for (int a = 0; a < 2; a++)
#pragma unroll
            for (int b = 0; b < 2; b++)
                wmma::fill_fragment(fc[p][a][b], 0.0f);

    int r_ld = tid >> 1;
    int hh = (tid & 1) << 4;                   // half offset 0 or 16
    const __half* gp[6];
    gp[0] = Ar + (size_t)(m0 + r_ld) * KDIM;
    gp[1] = Ai + (size_t)(m0 + r_ld) * KDIM;
    gp[2] = As + (size_t)(m0 + r_ld) * KDIM;
    gp[3] = Br + (size_t)(n0 + r_ld) * KDIM;
    gp[4] = Bi + (size_t)(n0 + r_ld) * KDIM;
    gp[5] = Bs + (size_t)(n0 + r_ld) * KDIM;
    int4 rv[6][2];
#pragma unroll
    for (int p = 0; p < 6; p++) {
        const int4* q = (const int4*)(gp[p] + hh);
        rv[p][0] = q[0]; rv[p][1] = q[1];
    }

    const int NS = KDIM / 32;                  // 64 stages
    for (int s = 0; s < NS; s++) {
        __syncthreads();                       // WAR: previous compute done
#pragma unroll
        for (int p = 0; p < 6; p++) {
            *(int4*)&pool[p][r_ld][hh]     = rv[p][0];
            *(int4*)&pool[p][r_ld][hh + 8] = rv[p][1];
        }
        __syncthreads();                       // RAW: tiles visible
        if (s + 1 < NS) {
            size_t kc = (size_t)(s + 1) << 5;
#pragma unroll
            for (int p = 0; p < 6; p++) {
                const int4* q = (const int4*)(gp[p] + kc + hh);
                rv[p][0] = q[0]; rv[p][1] = q[1];
            }
        }
#pragma unroll
        for (int k = 0; k < 2; k++) {
            int kh = k << 4;
#pragma unroll
            for (int p = 0; p < 3; p++) {
#pragma unroll
                for (int mi = 0; mi < 2; mi++)
                    wmma::load_matrix_sync(fa[p][mi], &pool[p][(wm << 5) + (mi << 4)][kh], SWK);
#pragma unroll
                for (int ni = 0; ni < 2; ni++)
                    wmma::load_matrix_sync(fb[p][ni], &pool[3 + p][(wn << 5) + (ni << 4)][kh], SWK);
            }
#pragma unroll
            for (int p = 0; p < 3; p++)
#pragma unroll
                for (int mi = 0; mi < 2; mi++)
#pragma unroll
                    for (int ni = 0; ni < 2; ni++)
                        wmma::mma_sync(fc[p][mi][ni], fa[p][mi], fb[p][ni], fc[p][mi][ni]);
        }
    }

    // ---------------- epilogue ----------------
    __syncthreads();
    float* sC = (float*)&pool[0][0][0] + wid * 256;   // 1KB per warp
    float mg = g_mag[sel];
    int r = lane >> 1, c0 = (lane & 1) << 3;
#pragma unroll
    for (int mi = 0; mi < 2; mi++) {
#pragma unroll
        for (int ni = 0; ni < 2; ni++) {
            int grow = m0 + (wm << 5) + (mi << 4) + r;
            int gcol = n0 + (wn << 5) + (ni << 4) + c0;
            float sc = mg * ts[grow];
            const float* src = sC + r * 16 + c0;
            float t1[8], t2[8], t3[8];

            wmma::store_matrix_sync(sC, fc[0][mi][ni], 16, wmma::mem_row_major);
            __syncwarp();
#pragma unroll
            for (int e = 0; e < 8; e++) t1[e] = src[e];
            __syncwarp();
            wmma::store_matrix_sync(sC, fc[1][mi][ni], 16, wmma::mem_row_major);
            __syncwarp();
#pragma unroll
            for (int e = 0; e < 8; e++) t2[e] = src[e];
            __syncwarp();
            wmma::store_matrix_sync(sC, fc[2][mi][ni], 16, wmma::mem_row_major);
            __syncwarp();
#pragma unroll
            for (int e = 0; e < 8; e++) t3[e] = src[e];
            __syncwarp();

            if (sel < 3) {
                float2* d2 = (float2*)dst2 + (size_t)grow * N + gcol;
#pragma unroll
                for (int e = 0; e < 8; e++) {
                    float2 o;
                    o.x = (t1[e] - t2[e]) * sc;
                    o.y = (t3[e] - t1[e] - t2[e]) * sc;
                    d2[e] = o;
                }
            } else {
                size_t gb = (size_t)grow * N + gcol;
                float4 o1, o2;
                o1.x = (t1[0]-t2[0])*sc; o1.y = (t1[1]-t2[1])*sc;
                o1.z = (t1[2]-t2[2])*sc; o1.w = (t1[3]-t2[3])*sc;
                o2.x = (t1[4]-t2[4])*sc; o2.y = (t1[5]-t2[5])*sc;
                o2.z = (t1[6]-t2[6])*sc; o2.w = (t1[7]-t2[7])*sc;
                *(float4*)(outr_p + gb)     = o1;
                *(float4*)(outr_p + gb + 4) = o2;
                o1.x = (t3[0]-t1[0]-t2[0])*sc; o1.y = (t3[1]-t1[1]-t2[1])*sc;
                o1.z = (t3[2]-t1[2]-t2[2])*sc; o1.w = (t3[3]-t1[3]-t2[3])*sc;
                o2.x = (t3[4]-t1[4]-t2[4])*sc; o2.y = (t3[5]-t1[5]-t2[5])*sc;
                o2.z = (t3[6]-t1[6]-t2[6])*sc; o2.w = (t3[7]-t1[7]-t2[7])*sc;
                *(float4*)(outi_p + gb)     = o1;
                *(float4*)(outi_p + gb + 4) = o2;
            }
        }
    }
}

// ---------------- RoPE on interleaved layout (re components only) ----------------
__global__ void rope_k(int sel) {
    float* x; int nh;
    if (sel == 0) { x = g_q2; nh = H_; } else { x = g_k2; nh = KV_; }
    int total = MTOK * nh * 64;
    int idx = blockIdx.x * blockDim.x + threadIdx.x;
    if (idx >= total) return;
    int d = idx & 63;
    int th = idx >> 6;
    int head = th % nh;
    int tok = th / nh;
    int pos = tok & (S_ - 1);
    float inv = (float)exp(-log(10000.0) * (double)d / 64.0);
    float ang = (float)pos * inv;
    float c = cosf(ang), sn = sinf(ang);
    size_t base = (size_t)tok * (nh * HD_ * 2) + head * (HD_ * 2);
    float x0 = x[base + 2 * d], x1 = x[base + 2 * d + 128];
    x[base + 2 * d]       = x0 * c - x1 * sn;
    x[base + 2 * d + 128] = x1 * c + x0 * sn;
}

// ---------------- causal attention: packed f32x2, 2 q-rows per warp ----------------
// grid (S/16, B*H), 256 thr; smem: sq 16x256f + sKV 32x260f = 49664B
#define ATTN_SMEM 49664
__global__ void __launch_bounds__(256) attn_k() {
    extern __shared__ float dyn[];
    float* sq  = dyn;            // [16][256]  (128 (re,im) pairs per row)
    float* sKV = dyn + 4096;     // [32][260]  (130 pair-slots; 128 used)
    int tid = threadIdx.x;
    int lane = tid & 31, w = tid >> 5;
    int b = blockIdx.y >> 4, h = blockIdx.y & 15;
    int kvh = h >> 2;
    int row0g = blockIdx.x << 4;
    int rl0 = w << 1, rl1 = rl0 + 1;
    int r0 = row0g + rl0, r1 = r0 + 1;
    // load q tile (interleaved pairs)
    for (int i = tid; i < 1024; i += 256) {
        int rl = i >> 6, off = i & 63;
        size_t src = ((size_t)(b * S_ + row0g + rl) * NQ + h * HD_) * 2 + off * 4;
        *(float4*)&sq[rl * 256 + off * 4] = *(const float4*)(g_q2 + src);
    }
    float m0 = -INFINITY, l0 = 0.f, m1 = -INFINITY, l1 = 0.f;
    unsigned long long o0[4] = {0,0,0,0}, o1[4] = {0,0,0,0};
    const float scale = 0.08838834764831845f;   // 1/sqrt(128)
    int nch = ((row0g + 15) >> 5) + 1;
    float p0 = 0.f, p1 = 0.f;
    for (int c = 0; c < nch; c++) {
        int k0 = c << 5;
        __syncthreads();
        // K tile
        for (int i = tid; i < 2048; i += 256) {
            int key = i >> 6, off = i & 63;
            size_t src = ((size_t)(b * S_ + k0 + key) * NKV + kvh * HD_) * 2 + off * 4;
            *(float4*)&sKV[key * 260 + off * 4] = *(const float4*)(g_k2 + src);
        }
        __syncthreads();
        bool act = (k0 <= r0);                  // warp-uniform
        p0 = 0.f; p1 = 0.f;
        if (act) {
            unsigned long long s0p = 0, s1p = 0;
            const ulonglong2* kr  = (const ulonglong2*)(sKV + lane * 260);
            const ulonglong2* q0p = (const ulonglong2*)(sq + rl0 * 256);
            const ulonglong2* q1p = (const ulonglong2*)(sq + rl1 * 256);
#pragma unroll 16
            for (int d4 = 0; d4 < 64; d4++) {
                ulonglong2 kk = kr[d4];
                ulonglong2 a0 = q0p[d4];
                ulonglong2 a1 = q1p[d4];
                FMA2(s0p, kk.x, a0.x); FMA2(s0p, kk.y, a0.y);
                FMA2(s1p, kk.x, a1.x); FMA2(s1p, kk.y, a1.y);
            }
            float lo, hi;
            upk2(lo, hi, s0p); float s0 = (lo + hi) * scale;
            upk2(lo, hi, s1p); float s1 = (lo + hi) * scale;
            if (k0 + lane > r0) s0 = -INFINITY;
            if (k0 + lane > r1) s1 = -INFINITY;
            // online softmax row0
            float cm = s0;
#pragma unroll
            for (int off = 16; off; off >>= 1)
                cm = fmaxf(cm, __shfl_xor_sync(0xffffffffu, cm, off));
            float mnew = fmaxf(m0, cm);
            p0 = expf(s0 - mnew);
            float corr = expf(m0 - mnew);
            float ps = p0;
#pragma unroll
            for (int off = 16; off; off >>= 1)
                ps += __shfl_xor_sync(0xffffffffu, ps, off);
            l0 = l0 * corr + ps;
            unsigned long long cp = pk2(corr, corr);
#pragma unroll
            for (int i = 0; i < 4; i++) MUL2(o0[i], cp);
            m0 = mnew;
            // online softmax row1
            cm = s1;
#pragma unroll
            for (int off = 16; off; off >>= 1)
                cm = fmaxf(cm, __shfl_xor_sync(0xffffffffu, cm, off));
            mnew = fmaxf(m1, cm);
            p1 = expf(s1 - mnew);
            corr = expf(m1 - mnew);
            ps = p1;
#pragma unroll
            for (int off = 16; off; off >>= 1)
                ps += __shfl_xor_sync(0xffffffffu, ps, off);
            l1 = l1 * corr + ps;
            cp = pk2(corr, corr);
#pragma unroll
            for (int i = 0; i < 4; i++) MUL2(o1[i], cp);
            m1 = mnew;
        }
        __syncthreads();
        // V tile (overwrite K buffer)
        for (int i = tid; i < 2048; i += 256) {
            int key = i >> 6, off = i & 63;
            size_t src = ((size_t)(b * S_ + k0 + key) * NKV + kvh * HD_) * 2 + off * 4;
            *(float4*)&sKV[key * 260 + off * 4] = *(const float4*)(g_v2 + src);
        }
        __syncthreads();
        if (act) {
            const unsigned long long* sV = (const unsigned long long*)sKV;  // 130 ull/row
#pragma unroll 8
            for (int j = 0; j < 32; j++) {
                float pj0 = __shfl_sync(0xffffffffu, p0, j);
                float pj1 = __shfl_sync(0xffffffffu, p1, j);
                unsigned long long pp0 = pk2(pj0, pj0);
                unsigned long long pp1 = pk2(pj1, pj1);
                int base = j * 130 + lane;
#pragma unroll
                for (int i = 0; i < 4; i++) {
                    unsigned long long v = sV[base + (i << 5)];
                    FMA2(o0[i], v, pp0);
                    FMA2(o1[i], v, pp1);
                }
            }
        }
    }
    float inv0 = 1.f / l0, inv1 = 1.f / l1;
    size_t p0off = (size_t)(b * S_ + r0) * NQ + h * HD_;
    size_t p1off = (size_t)(b * S_ + r1) * NQ + h * HD_;
    float2* o2 = (float2*)g_o2;
#pragma unroll
    for (int i = 0; i < 4; i++) {
        float re, im;
        upk2(re, im, o0[i]);
        o2[p0off + lane + (i << 5)] = make_float2(re * inv0, im * inv0);
        upk2(re, im, o1[i]);
        o2[p1off + lane + (i << 5)] = make_float2(re * inv1, im * inv1);
    }
}

// ---------------- launch ----------------
extern "C" void kernel_launch(void* const* d_in, const int* in_sizes, int n_in,
                              void* d_out, int out_size) {
    const float* hr  = (const float*)d_in[0];
    const float* hi  = (const float*)d_in[1];
    const float* wqr = (const float*)d_in[2];
    const float* wqi = (const float*)d_in[3];
    const float* wkr = (const float*)d_in[4];
    const float* wki = (const float*)d_in[5];
    const float* wvr = (const float*)d_in[6];
    const float* wvi = (const float*)d_in[7];
    const float* wor = (const float*)d_in[8];
    const float* woi = (const float*)d_in[9];
    float* out = (float*)d_out;

    cudaFuncSetAttribute(attn_k, cudaFuncAttributeMaxDynamicSharedMemorySize, ATTN_SMEM);

    dim3 tb(32, 8);
    tern_T<<<dim3(NQ / 32, D_ / 32), tb>>>(wqr, wqi, 0, D_, NQ);
    tern_T<<<dim3(NKV / 32, D_ / 32), tb>>>(wkr, wki, 1, D_, NKV);
    tern_T<<<dim3(NKV / 32, D_ / 32), tb>>>(wvr, wvi, 2, D_, NKV);
    tern_T<<<dim3(D_ / 32, NQ / 32), tb>>>(wor, woi, 3, NQ, D_);
    mag_final2<<<4, 256>>>();

    act_quant_k<<<MTOK, 256>>>(hr, hi, 0);

    gemm_cplx_wmma<<<dim3(NQ / 64, MTOK / 64), 128>>>(0, nullptr, nullptr);
    gemm_cplx_wmma<<<dim3(NKV / 64, MTOK / 64), 128>>>(1, nullptr, nullptr);
    gemm_cplx_wmma<<<dim3(NKV / 64, MTOK / 64), 128>>>(2, nullptr, nullptr);

    rope_k<<<(MTOK * H_ * 64) / 256, 256>>>(0);
    rope_k<<<(MTOK * KV_ * 64) / 256, 256>>>(1);

    attn_k<<<dim3(S_ / 16, B_ * H_), 256, ATTN_SMEM>>>();

    act_quant_k<<<MTOK, 256>>>(nullptr, nullptr, 1);

    gemm_cplx_wmma<<<dim3(NQ / 64, MTOK / 64), 128>>>(3, out, out + (size_t)B_ * S_ * D_);
}